// round 10
// baseline (speedup 1.0000x reference)
#include <cuda_runtime.h>
#include <cuda_bf16.h>
#include <cstdint>

#define BSZ  512
#define TLEN 512
#define IDIM 128
#define HDIM 50
#define ODIM 10
#define GDIM 200              // 4*H
#define BT   (BSZ * TLEN)     // 262144 rows

typedef unsigned long long u64;
typedef unsigned int u32;

// ---- scratch (device globals; no allocation allowed) ----
__device__ u32   g_Bimg[102400 / 4];   // W bf16 hi/lo, mma-fragment-ordered
__device__ float g_bias[GDIM];         // b_ih + b_hh
__device__ float g_xp[BT * GDIM];      // x_proj: [row][g]

// ---- packed f32x2 helpers ----
__device__ __forceinline__ u64 pk2(float lo, float hi) {
    u64 d;
    asm("mov.b64 %0, {%1, %2};" : "=l"(d) : "f"(lo), "f"(hi));
    return d;
}
__device__ __forceinline__ void up2(u64 v, float& lo, float& hi) {
    asm("mov.b64 {%0, %1}, %2;" : "=f"(lo), "=f"(hi) : "l"(v));
}
__device__ __forceinline__ u64 ffma2(u64 a, u64 b, u64 c) {
    u64 d;
    asm("fma.rn.f32x2 %0, %1, %2, %3;" : "=l"(d) : "l"(a), "l"(b), "l"(c));
    return d;
}
__device__ __forceinline__ u64 fadd2(u64 a, u64 b) {
    u64 d;
    asm("add.rn.f32x2 %0, %1, %2;" : "=l"(d) : "l"(a), "l"(b));
    return d;
}
__device__ __forceinline__ float fast_sigmoid(float x) {
    return 1.f / (1.f + __expf(-x));
}
__device__ __forceinline__ void cp16(void* smem, const void* gmem) {
    unsigned sa = (unsigned)__cvta_generic_to_shared(smem);
    asm volatile("cp.async.cg.shared.global [%0], [%1], 16;\n" :: "r"(sa), "l"(gmem));
}

// hi/lo bf16 split of one float
__device__ __forceinline__ void split_bf16(float v, unsigned short& h, unsigned short& l) {
    __nv_bfloat16 hb = __float2bfloat16_rn(v);
    float lf = v - __bfloat162float(hb);
    __nv_bfloat16 lb = __float2bfloat16_rn(lf);
    h = __bfloat16_as_ushort(hb);
    l = __bfloat16_as_ushort(lb);
}

// mma.sync m16n8k16 row.col f32.bf16.bf16.f32
__device__ __forceinline__ void mma16816(float* c, const u32* a, u32 b0, u32 b1) {
    asm volatile(
        "mma.sync.aligned.m16n8k16.row.col.f32.bf16.bf16.f32 "
        "{%0,%1,%2,%3}, {%4,%5,%6,%7}, {%8,%9}, {%0,%1,%2,%3};"
        : "+f"(c[0]), "+f"(c[1]), "+f"(c[2]), "+f"(c[3])
        : "r"(a[0]), "r"(a[1]), "r"(a[2]), "r"(a[3]), "r"(b0), "r"(b1));
}

// ============================================================
// Kernel 0: build W fragment-ordered bf16 hi/lo image + bias.
// ============================================================
__global__ void prep(const float* __restrict__ W_ih,
                     const float* __restrict__ b_ih,
                     const float* __restrict__ b_hh) {
    int t = threadIdx.x + blockIdx.x * 256;
    for (int idx = t; idx < GDIM * (IDIM / 2); idx += 256 * 32) {
        int g  = idx >> 6;
        int k2 = (idx & 63) * 2;
        unsigned short h0, l0, h1, l1;
        split_bf16(W_ih[g * IDIM + k2],     h0, l0);
        split_bf16(W_ih[g * IDIM + k2 + 1], h1, l1);
        u32 hp = (u32)h0 | ((u32)h1 << 16);
        u32 lp = (u32)l0 | ((u32)l1 << 16);
        int nt = g >> 3, nloc = g & 7;
        int kc = k2 >> 4, kloc = k2 & 15;
        int lane = nloc * 4 + ((kloc & 7) >> 1);
        int reg  = kloc >> 3;
        int base = ((kc * 25 + nt) * 32 + lane) * 4;
        g_Bimg[base + reg]     = hp;
        g_Bimg[base + 2 + reg] = lp;
    }
    if (blockIdx.x == 0 && t < GDIM) g_bias[t] = b_ih[t] + b_hh[t];
}

// ============================================================
// Kernel 1: HMMA GEMM, bf16 hi/lo split, fp32 accum.
// Block: 512 thr (16 warps), tile M=128 x N=200 x K=128.
// Warp w: m-tile (w&7), n-half (w>>3): 13 or 12 n-tiles.
// ============================================================
#define SM_AHI  0
#define SM_ALO  32768
#define SM_B    65536            // 102400 B
#define SM_BIAS 167936           // 800 B
#define MMA_SMEM 168960

__global__ __launch_bounds__(512, 1) void gemm_mma(const float* __restrict__ x) {
    extern __shared__ char sm[];
    u32*   aHi  = (u32*)(sm + SM_AHI);
    u32*   aLo  = (u32*)(sm + SM_ALO);
    u32*   bImg = (u32*)(sm + SM_B);
    float* bias = (float*)(sm + SM_BIAS);

    const int tid = threadIdx.x;
    const int w   = tid >> 5;
    const int l   = tid & 31;
    const int row0 = blockIdx.x * 128;

    // B image: 6400 x 16B chunks (async): 12 full rounds + 256-tail
#pragma unroll
    for (int u = 0; u < 12; u++) {
        int idx = tid + u * 512;
        cp16(bImg + idx * 4, g_Bimg + idx * 4);
    }
    if (tid < 256) {
        int idx = 6144 + tid;
        cp16(bImg + idx * 4, g_Bimg + idx * 4);
    }
    asm volatile("cp.async.commit_group;\n" ::: "memory");

    if (tid < GDIM) bias[tid] = g_bias[tid];

    // A: convert x tile (128 rows x 128 k) to bf16 hi/lo fragments.
    // 4096 float4 chunks = 8 per thread.
#pragma unroll
    for (int i = 0; i < 8; i++) {
        int idx = tid + i * 512;
        int r  = idx >> 5;
        int k4 = (idx & 31) * 4;
        float4 v = *(const float4*)&x[(size_t)(row0 + r) * IDIM + k4];
#pragma unroll
        for (int p = 0; p < 2; p++) {
            int k2 = k4 + 2 * p;
            float e0 = p ? v.z : v.x;
            float e1 = p ? v.w : v.y;
            unsigned short h0, l0, h1, l1;
            split_bf16(e0, h0, l0);
            split_bf16(e1, h1, l1);
            u32 hp = (u32)h0 | ((u32)h1 << 16);
            u32 lp = (u32)l0 | ((u32)l1 << 16);
            int m = r >> 4, rloc = r & 15;
            int kc = k2 >> 4, kloc = k2 & 15;
            int lane = (rloc & 7) * 4 + ((kloc & 7) >> 1);
            int reg  = (kloc >> 3) * 2 + (rloc >> 3);
            int a4   = ((m * 8 + kc) * 32 + lane) * 4 + reg;
            aHi[a4] = hp;
            aLo[a4] = lp;
        }
    }

    asm volatile("cp.async.wait_group 0;\n" ::: "memory");
    __syncthreads();

    // compute: warp w -> m-tile mt, n-tiles [n0, n0+cnt)
    const int mt = w & 7;
    const int nh = w >> 3;
    const int n0 = nh * 13;
    const int cnt = nh ? 12 : 13;

    float acc[13][4];
#pragma unroll
    for (int n = 0; n < 13; n++)
#pragma unroll
        for (int j = 0; j < 4; j++) acc[n][j] = 0.f;

#pragma unroll
    for (int kc = 0; kc < 8; kc++) {
        uint4 ah = *(const uint4*)&aHi[((mt * 8 + kc) * 32 + l) * 4];
        uint4 al = *(const uint4*)&aLo[((mt * 8 + kc) * 32 + l) * 4];
        u32 ahr[4] = {ah.x, ah.y, ah.z, ah.w};
        u32 alr[4] = {al.x, al.y, al.z, al.w};
#pragma unroll
        for (int n = 0; n < 13; n++) {
            if (n < cnt) {
                uint4 b = *(const uint4*)&bImg[((kc * 25 + n0 + n) * 32 + l) * 4];
                mma16816(acc[n], ahr, b.x, b.y);   // hi * hi
                mma16816(acc[n], ahr, b.z, b.w);   // hi * lo
                mma16816(acc[n], alr, b.x, b.y);   // lo * hi
            }
        }
    }

    // epilogue
    {
        int r0 = row0 + mt * 16 + (l >> 2);
        int r1 = r0 + 8;
#pragma unroll
        for (int n = 0; n < 13; n++) {
            if (n < cnt) {
                int c = (n0 + n) * 8 + (l & 3) * 2;
                float2 bv = *(const float2*)&bias[c];
                float2 o0 = make_float2(acc[n][0] + bv.x, acc[n][1] + bv.y);
                float2 o1 = make_float2(acc[n][2] + bv.x, acc[n][3] + bv.y);
                *(float2*)&g_xp[(size_t)r0 * GDIM + c] = o0;
                *(float2*)&g_xp[(size_t)r1 * GDIM + c] = o1;
            }
        }
    }
}

// ============================================================
// Kernel 2: LSTM recurrence + FC head, quad-gate mapping.
// Thread tau: unit u = tau>>2, gate q = tau&3 (gate row q*50+u).
// All 4 gates of a unit live in one warp QUAD -> gate exchange by
// SHFL, c/h update in lane q=0, h double-buffered in SMEM ->
// ONE __syncthreads per timestep.
// ============================================================
__global__ __launch_bounds__(224, 2) void lstm_rec(
    const float* __restrict__ W_hh, const float* __restrict__ W_fc,
    const float* __restrict__ b_fc, float* __restrict__ out)
{
    __shared__ alignas(16) float2 h_sh[2][HDIM];
    const int b0 = blockIdx.x * 2;
    const int tau = threadIdx.x;
    const int u = tau >> 2;
    const int q = tau & 3;
    const bool act_th = (tau < 4 * HDIM);      // 200 active
    const int grow = q * HDIM + u;             // gate row (PyTorch i,f,g,o)
    const int lb = (tau & 31) & ~3;            // quad base lane

    u64 w2[HDIM];
    if (act_th) {
#pragma unroll
        for (int j = 0; j < HDIM; j++) {
            float wv = W_hh[grow * HDIM + j];
            w2[j] = pk2(wv, wv);
        }
    }
    if (tau < HDIM) h_sh[0][tau] = make_float2(0.f, 0.f);
    float c0 = 0.f, c1 = 0.f;

    const float* xp0 = g_xp + (size_t)b0 * (TLEN * GDIM);
    const float* xp1 = xp0 + (size_t)(TLEN * GDIM);
    float xc0 = 0.f, xc1 = 0.f;
    if (act_th) { xc0 = xp0[grow]; xc1 = xp1[grow]; }
    __syncthreads();

    int pb = 0;
    for (int t = 0; t < TLEN; t++) {
        float r0 = 0.f, r1 = 0.f;
        if (act_th) {
            u64 A0 = pk2(xc0, xc1), A1 = 0ull, A2 = 0ull, A3 = 0ull;
            if (t + 1 < TLEN) {                  // prefetch next step
                xc0 = xp0[(t + 1) * GDIM + grow];
                xc1 = xp1[(t + 1) * GDIM + grow];
            }
            const float2* hb = h_sh[pb];
#pragma unroll
            for (int j = 0; j < 48; j += 4) {
                ulonglong2 hv0 = *(const ulonglong2*)(hb + j);
                ulonglong2 hv1 = *(const ulonglong2*)(hb + j + 2);
                A0 = ffma2(hv0.x, w2[j],     A0);
                A1 = ffma2(hv0.y, w2[j + 1], A1);
                A2 = ffma2(hv1.x, w2[j + 2], A2);
                A3 = ffma2(hv1.y, w2[j + 3], A3);
            }
            {
                ulonglong2 hv = *(const ulonglong2*)(hb + 48);
                A0 = ffma2(hv.x, w2[48], A0);
                A1 = ffma2(hv.y, w2[49], A1);
            }
            float a0, a1;
            up2(fadd2(fadd2(A0, A2), fadd2(A1, A3)), a0, a1);
            bool isg = (q == 2);                 // tanh gate
            float z0 = isg ? (a0 + a0) : a0;
            float z1 = isg ? (a1 + a1) : a1;
            float s0 = fast_sigmoid(z0);
            float s1 = fast_sigmoid(z1);
            r0 = isg ? (2.f * s0 - 1.f) : s0;
            r1 = isg ? (2.f * s1 - 1.f) : s1;
        }
        // quad exchange (warp-converged: shuffles outside the predicate)
        float iv0 = __shfl_sync(0xffffffffu, r0, lb + 0);
        float iv1 = __shfl_sync(0xffffffffu, r1, lb + 0);
        float fv0 = __shfl_sync(0xffffffffu, r0, lb + 1);
        float fv1 = __shfl_sync(0xffffffffu, r1, lb + 1);
        float gv0 = __shfl_sync(0xffffffffu, r0, lb + 2);
        float gv1 = __shfl_sync(0xffffffffu, r1, lb + 2);
        float ov0 = __shfl_sync(0xffffffffu, r0, lb + 3);
        float ov1 = __shfl_sync(0xffffffffu, r1, lb + 3);
        if (act_th && q == 0) {
            c0 = fmaf(fv0, c0, iv0 * gv0);
            c1 = fmaf(fv1, c1, iv1 * gv1);
            float th0 = 2.f * fast_sigmoid(c0 + c0) - 1.f;   // tanh(c0)
            float th1 = 2.f * fast_sigmoid(c1 + c1) - 1.f;
            h_sh[pb ^ 1][u] = make_float2(ov0 * th0, ov1 * th1);
        }
        __syncthreads();
        pb ^= 1;
    }

    // FC head for both batches (final h in h_sh[pb])
    if (tau < ODIM) {
        float a0 = b_fc[tau], a1 = a0;
#pragma unroll
        for (int j = 0; j < HDIM; j++) {
            float2 h = h_sh[pb][j];
            float wv = W_fc[tau * HDIM + j];
            a0 = fmaf(h.x, wv, a0);
            a1 = fmaf(h.y, wv, a1);
        }
        out[b0 * ODIM + tau]       = a0;
        out[(b0 + 1) * ODIM + tau] = a1;
    }
}

// ============================================================
// Launch
// ============================================================
extern "C" void kernel_launch(void* const* d_in, const int* in_sizes, int n_in,
                              void* d_out, int out_size) {
    const float* x    = (const float*)d_in[0];
    const float* W_ih = (const float*)d_in[1];
    const float* W_hh = (const float*)d_in[2];
    const float* b_ih = (const float*)d_in[3];
    const float* b_hh = (const float*)d_in[4];
    const float* W_fc = (const float*)d_in[5];
    const float* b_fc = (const float*)d_in[6];
    float* out = (float*)d_out;

    cudaFuncSetAttribute(gemm_mma, cudaFuncAttributeMaxDynamicSharedMemorySize,
                         MMA_SMEM);

    prep<<<32, 256>>>(W_ih, b_ih, b_hh);
    gemm_mma<<<BT / 128, 512, MMA_SMEM>>>(x);
    lstm_rec<<<BSZ / 2, 224>>>(W_hh, W_fc, b_fc, out);
}

// round 11
// speedup vs baseline: 1.1300x; 1.1300x over previous
#include <cuda_runtime.h>
#include <cuda_bf16.h>
#include <cstdint>

#define BSZ  512
#define TLEN 512
#define IDIM 128
#define HDIM 50
#define ODIM 10
#define GDIM 200              // 4*H
#define BT   (BSZ * TLEN)     // 262144 rows

typedef unsigned long long u64;
typedef unsigned int u32;

// ---- scratch (device globals; no allocation allowed) ----
__device__ u32   g_Bimg[102400 / 4];   // W bf16 hi/lo, mma-fragment-ordered
__device__ float g_bias[GDIM];         // b_ih + b_hh
__device__ float g_xp[BT * GDIM];      // x_proj: [row][g]

// ---- packed f32x2 helpers ----
__device__ __forceinline__ u64 pk2(float lo, float hi) {
    u64 d;
    asm("mov.b64 %0, {%1, %2};" : "=l"(d) : "f"(lo), "f"(hi));
    return d;
}
__device__ __forceinline__ void up2(u64 v, float& lo, float& hi) {
    asm("mov.b64 {%0, %1}, %2;" : "=f"(lo), "=f"(hi) : "l"(v));
}
__device__ __forceinline__ u64 ffma2(u64 a, u64 b, u64 c) {
    u64 d;
    asm("fma.rn.f32x2 %0, %1, %2, %3;" : "=l"(d) : "l"(a), "l"(b), "l"(c));
    return d;
}
__device__ __forceinline__ u64 fadd2(u64 a, u64 b) {
    u64 d;
    asm("add.rn.f32x2 %0, %1, %2;" : "=l"(d) : "l"(a), "l"(b));
    return d;
}
__device__ __forceinline__ float fast_sigmoid(float x) {
    return 1.f / (1.f + __expf(-x));
}
__device__ __forceinline__ void cp16(void* smem, const void* gmem) {
    unsigned sa = (unsigned)__cvta_generic_to_shared(smem);
    asm volatile("cp.async.cg.shared.global [%0], [%1], 16;\n" :: "r"(sa), "l"(gmem));
}

// hi/lo bf16 split of one float
__device__ __forceinline__ void split_bf16(float v, unsigned short& h, unsigned short& l) {
    __nv_bfloat16 hb = __float2bfloat16_rn(v);
    float lf = v - __bfloat162float(hb);
    __nv_bfloat16 lb = __float2bfloat16_rn(lf);
    h = __bfloat16_as_ushort(hb);
    l = __bfloat16_as_ushort(lb);
}
// split a float2 into packed-hi u32 and packed-lo u32
__device__ __forceinline__ void split2(float2 v, u32& hp, u32& lp) {
    unsigned short h0, l0, h1, l1;
    split_bf16(v.x, h0, l0);
    split_bf16(v.y, h1, l1);
    hp = (u32)h0 | ((u32)h1 << 16);
    lp = (u32)l0 | ((u32)l1 << 16);
}

// mma.sync m16n8k16 row.col f32.bf16.bf16.f32
__device__ __forceinline__ void mma16816(float* c, const u32* a, u32 b0, u32 b1) {
    asm volatile(
        "mma.sync.aligned.m16n8k16.row.col.f32.bf16.bf16.f32 "
        "{%0,%1,%2,%3}, {%4,%5,%6,%7}, {%8,%9}, {%0,%1,%2,%3};"
        : "+f"(c[0]), "+f"(c[1]), "+f"(c[2]), "+f"(c[3])
        : "r"(a[0]), "r"(a[1]), "r"(a[2]), "r"(a[3]), "r"(b0), "r"(b1));
}

// ============================================================
// Kernel 0: build W fragment-ordered bf16 hi/lo image + bias.
// B frag (m16n8k16 col-major B): lane = (n&7)*4 + ((k&7)>>1),
// b0: k<8, b1: k>=8. Per-lane 16B = {b0hi, b1hi, b0lo, b1lo}.
// ============================================================
__global__ void prep(const float* __restrict__ W_ih,
                     const float* __restrict__ b_ih,
                     const float* __restrict__ b_hh) {
    int t = threadIdx.x + blockIdx.x * 256;
    for (int idx = t; idx < GDIM * (IDIM / 2); idx += 256 * 32) {
        int g  = idx >> 6;
        int k2 = (idx & 63) * 2;
        u32 hp, lp;
        split2(*(const float2*)&W_ih[g * IDIM + k2], hp, lp);
        int nt = g >> 3, nloc = g & 7;
        int kc = k2 >> 4, kloc = k2 & 15;
        int lane = nloc * 4 + ((kloc & 7) >> 1);
        int reg  = kloc >> 3;
        int base = ((kc * 25 + nt) * 32 + lane) * 4;
        g_Bimg[base + reg]     = hp;
        g_Bimg[base + 2 + reg] = lp;
    }
    if (blockIdx.x == 0 && t < GDIM) g_bias[t] = b_ih[t] + b_hh[t];
}

// ============================================================
// Kernel 1: HMMA GEMM, bf16 hi/lo split, fp32 accum.
// A fragments loaded DIRECTLY from gmem into registers (per-lane
// LDG.64 at the m16n8k16 lane mapping), hi/lo split in regs.
// B image cp.async -> SMEM (only SMEM user, 103KB).
// Block: 512 thr / 16 warps: warp w -> m-tile (w&7), n-half (w>>3).
// ============================================================
#define SM_B    0                // 102400 B
#define SM_BIAS 102400           // 800 B
#define MMA_SMEM 103296

__global__ __launch_bounds__(512, 1) void gemm_mma(const float* __restrict__ x) {
    extern __shared__ char sm[];
    u32*   bImg = (u32*)(sm + SM_B);
    float* bias = (float*)(sm + SM_BIAS);

    const int tid = threadIdx.x;
    const int w   = tid >> 5;
    const int l   = tid & 31;
    const int row0 = blockIdx.x * 128;

    // B image: 6400 x 16B chunks (async): 12 full rounds + 256-tail
#pragma unroll
    for (int u = 0; u < 12; u++) {
        int idx = tid + u * 512;
        cp16(bImg + idx * 4, g_Bimg + idx * 4);
    }
    if (tid < 256) {
        int idx = 6144 + tid;
        cp16(bImg + idx * 4, g_Bimg + idx * 4);
    }
    asm volatile("cp.async.commit_group;\n" ::: "memory");
    if (tid < GDIM) bias[tid] = g_bias[tid];

    // warp assignment
    const int mt  = w & 7;
    const int nh  = w >> 3;
    const int n0  = nh * 13;
    const int cnt = nh ? 12 : 13;

    // per-lane A addresses: reg0=(r,klo) reg1=(r+8,klo) reg2=(r,khi) reg3=(r+8,khi)
    const int rA = row0 + mt * 16 + (l >> 2);
    const float* xr0 = x + (size_t)rA * IDIM + (l & 3) * 2;       // row r
    const float* xr1 = xr0 + 8 * IDIM;                            // row r+8

    float acc[13][4];
#pragma unroll
    for (int n = 0; n < 13; n++)
#pragma unroll
        for (int j = 0; j < 4; j++) acc[n][j] = 0.f;

    // prefetch kc=0 A data before waiting on B
    float2 v0 = *(const float2*)(xr0);
    float2 v1 = *(const float2*)(xr1);
    float2 v2 = *(const float2*)(xr0 + 8);
    float2 v3 = *(const float2*)(xr1 + 8);

    asm volatile("cp.async.wait_group 0;\n" ::: "memory");
    __syncthreads();

#pragma unroll
    for (int kc = 0; kc < 8; kc++) {
        u32 ahr[4], alr[4];
        split2(v0, ahr[0], alr[0]);
        split2(v1, ahr[1], alr[1]);
        split2(v2, ahr[2], alr[2]);
        split2(v3, ahr[3], alr[3]);
        if (kc + 1 < 8) {                      // prefetch next k-chunk
            int ko = (kc + 1) * 16;
            v0 = *(const float2*)(xr0 + ko);
            v1 = *(const float2*)(xr1 + ko);
            v2 = *(const float2*)(xr0 + ko + 8);
            v3 = *(const float2*)(xr1 + ko + 8);
        }
#pragma unroll
        for (int n = 0; n < 13; n++) {
            if (n < cnt) {
                uint4 b = *(const uint4*)&bImg[((kc * 25 + n0 + n) * 32 + l) * 4];
                mma16816(acc[n], ahr, b.x, b.y);   // hi * hi
                mma16816(acc[n], ahr, b.z, b.w);   // hi * lo
                mma16816(acc[n], alr, b.x, b.y);   // lo * hi
            }
        }
    }

    // epilogue: D frag c0/c1: row=l>>2, col=(l&3)*2; c2/c3: row+8.
    {
        int r0 = row0 + mt * 16 + (l >> 2);
        int r1 = r0 + 8;
#pragma unroll
        for (int n = 0; n < 13; n++) {
            if (n < cnt) {
                int c = (n0 + n) * 8 + (l & 3) * 2;
                float2 bv = *(const float2*)&bias[c];
                float2 o0 = make_float2(acc[n][0] + bv.x, acc[n][1] + bv.y);
                float2 o1 = make_float2(acc[n][2] + bv.x, acc[n][3] + bv.y);
                *(float2*)&g_xp[(size_t)r0 * GDIM + c] = o0;
                *(float2*)&g_xp[(size_t)r1 * GDIM + c] = o1;
            }
        }
    }
}

// ============================================================
// Kernel 2: LSTM recurrence + FC head (R3 version, measured 361us).
// 2 batches/block, grid 256, W_hh dup-pairs in registers.
// ============================================================
__global__ __launch_bounds__(224, 2) void lstm_rec(
    const float* __restrict__ W_hh, const float* __restrict__ W_fc,
    const float* __restrict__ b_fc, float* __restrict__ out)
{
    __shared__ alignas(16) float2 h_sh[HDIM];
    __shared__ alignas(16) float2 gate_sh[GDIM];
    const int b0 = blockIdx.x * 2;
    const int g = threadIdx.x;

    u64 w2[HDIM];
    if (g < GDIM) {
#pragma unroll
        for (int j = 0; j < HDIM; j++) {
            float w = W_hh[g * HDIM + j];
            w2[j] = pk2(w, w);
        }
    }
    if (g < HDIM) h_sh[g] = make_float2(0.f, 0.f);
    float c0 = 0.f, c1 = 0.f;

    const float* xp0 = g_xp + (size_t)b0 * (TLEN * GDIM);
    const float* xp1 = xp0 + (size_t)(TLEN * GDIM);
    float xc0 = 0.f, xc1 = 0.f;
    if (g < GDIM) { xc0 = xp0[g]; xc1 = xp1[g]; }
    const bool isg = (g >= 2 * HDIM && g < 3 * HDIM);   // tanh gate
    __syncthreads();

    for (int t = 0; t < TLEN; t++) {
        if (g < GDIM) {
            u64 accA = pk2(xc0, xc1);
            u64 accB = 0ull;
            if (t + 1 < TLEN) {                          // prefetch next step
                xc0 = xp0[(t + 1) * GDIM + g];
                xc1 = xp1[(t + 1) * GDIM + g];
            }
#pragma unroll
            for (int j = 0; j < HDIM; j += 2) {
                ulonglong2 hv = *(const ulonglong2*)(h_sh + j);
                accA = ffma2(hv.x, w2[j],     accA);
                accB = ffma2(hv.y, w2[j + 1], accB);
            }
            float a0, a1;
            up2(fadd2(accA, accB), a0, a1);
            float z0 = isg ? (a0 + a0) : a0;
            float z1 = isg ? (a1 + a1) : a1;
            float s0 = fast_sigmoid(z0);
            float s1 = fast_sigmoid(z1);
            float r0 = isg ? (2.f * s0 - 1.f) : s0;
            float r1 = isg ? (2.f * s1 - 1.f) : s1;
            gate_sh[g] = make_float2(r0, r1);
        }
        __syncthreads();
        if (g < HDIM) {
            float2 iv = gate_sh[g];
            float2 fv = gate_sh[g + HDIM];
            float2 gv = gate_sh[g + 2 * HDIM];
            float2 ov = gate_sh[g + 3 * HDIM];
            c0 = fmaf(fv.x, c0, iv.x * gv.x);
            c1 = fmaf(fv.y, c1, iv.y * gv.y);
            float th0 = 2.f * fast_sigmoid(c0 + c0) - 1.f;
            float th1 = 2.f * fast_sigmoid(c1 + c1) - 1.f;
            h_sh[g] = make_float2(ov.x * th0, ov.y * th1);
        }
        __syncthreads();
    }

    // FC head for both batches
    if (g < ODIM) {
        float a0 = b_fc[g], a1 = a0;
#pragma unroll
        for (int j = 0; j < HDIM; j++) {
            float2 h = h_sh[j];
            float w = W_fc[g * HDIM + j];
            a0 = fmaf(h.x, w, a0);
            a1 = fmaf(h.y, w, a1);
        }
        out[b0 * ODIM + g]       = a0;
        out[(b0 + 1) * ODIM + g] = a1;
    }
}

// ============================================================
// Launch
// ============================================================
extern "C" void kernel_launch(void* const* d_in, const int* in_sizes, int n_in,
                              void* d_out, int out_size) {
    const float* x    = (const float*)d_in[0];
    const float* W_ih = (const float*)d_in[1];
    const float* W_hh = (const float*)d_in[2];
    const float* b_ih = (const float*)d_in[3];
    const float* b_hh = (const float*)d_in[4];
    const float* W_fc = (const float*)d_in[5];
    const float* b_fc = (const float*)d_in[6];
    float* out = (float*)d_out;

    cudaFuncSetAttribute(gemm_mma, cudaFuncAttributeMaxDynamicSharedMemorySize,
                         MMA_SMEM);

    prep<<<32, 256>>>(W_ih, b_ih, b_hh);
    gemm_mma<<<BT / 128, 512, MMA_SMEM>>>(x);
    lstm_rec<<<BSZ / 2, 224>>>(W_hh, W_fc, b_fc, out);
}